// round 1
// baseline (speedup 1.0000x reference)
#include <cuda_runtime.h>

#define NBOX        1048576
#define BOX_PER_BLK 256
#define NBLOCKS     (NBOX / BOX_PER_BLK)   // 4096
#define PRED_F      18                      // floats per box in pred (9 pts * 2)
#define TGT_F       8                       // floats per box in target (4 pts * 2)

// Scratch for block partial sums (no device allocation allowed).
__device__ float g_partials[NBLOCKS];

__global__ __launch_bounds__(BOX_PER_BLK)
void kld_main_kernel(const float* __restrict__ pred, const float* __restrict__ tgt)
{
    __shared__ float sp[BOX_PER_BLK * PRED_F];   // 4608 floats = 18432 B
    __shared__ float st[BOX_PER_BLK * TGT_F];    // 2048 floats =  8192 B
    __shared__ float red[8];

    const int tid = threadIdx.x;
    const int blk = blockIdx.x;

    // ---- Coalesced staging: global -> shared via float4 ----
    {
        const float4* p4 = (const float4*)(pred + (size_t)blk * (BOX_PER_BLK * PRED_F));
        float4*       s4 = (float4*)sp;
        #pragma unroll
        for (int i = tid; i < (BOX_PER_BLK * PRED_F) / 4; i += BOX_PER_BLK)
            s4[i] = p4[i];

        const float4* t4 = (const float4*)(tgt + (size_t)blk * (BOX_PER_BLK * TGT_F));
        float4*       q4 = (float4*)st;
        #pragma unroll
        for (int i = tid; i < (BOX_PER_BLK * TGT_F) / 4; i += BOX_PER_BLK)
            q4[i] = t4[i];
    }
    __syncthreads();

    // ---- Per-box math ----
    const float* pb = sp + tid * PRED_F;
    const float* tb = st + tid * TGT_F;

    // pred mean (9 points)
    float mux = 0.f, muy = 0.f;
    #pragma unroll
    for (int k = 0; k < 9; ++k) { mux += pb[2*k]; muy += pb[2*k + 1]; }
    const float inv9 = 1.0f / 9.0f;
    mux *= inv9; muy *= inv9;

    // centered covariance (two-pass for precision)
    float sxx = 0.f, sxy = 0.f, syy = 0.f;
    #pragma unroll
    for (int k = 0; k < 9; ++k) {
        float dx = pb[2*k]     - mux;
        float dy = pb[2*k + 1] - muy;
        sxx += dx * dx; sxy += dx * dy; syy += dy * dy;
    }
    const float GMM_EPS = 1e-6f;
    float pxx = sxx * inv9 + GMM_EPS;
    float pxy = sxy * inv9;
    float pyy = syy * inv9 + GMM_EPS;

    // target: 4 corners
    float x0 = tb[0], y0 = tb[1];
    float x1 = tb[2], y1 = tb[3];
    float x2 = tb[4], y2 = tb[5];
    float x3 = tb[6], y3 = tb[7];

    float tmux = (x0 + x1 + x2 + x3) * 0.25f;
    float tmuy = (y0 + y1 + y2 + y3) * 0.25f;

    float e1x = x1 - x0, e1y = y1 - y0;
    float e2x = x2 - x1, e2y = y2 - y1;
    float w = e1x * e1x + e1y * e1y;
    float h = e2x * e2x + e2y * e2y;

    float inv_sw = rsqrtf(w);
    float c = e1x * inv_sw;
    float s = e1y * inv_sw;

    const float invLL = 1.0f / 36.0f;     // 1/(4*L*L), L=3
    float d0 = w * invLL;
    float d1 = h * invLL;

    float txx = c * c * d0 + s * s * d1;
    float txy = c * s * (d0 - d1);
    float tyy = s * s * d0 + c * c * d1;

    float tdet = txx * tyy - txy * txy;
    float invd = 1.0f / tdet;
    float ixx =  tyy * invd;
    float ixy = -txy * invd;
    float iyy =  txx * invd;

    float dx = mux - tmux;
    float dy = muy - tmuy;

    float term1 = dx * dx * ixx + 2.0f * dx * dy * ixy + dy * dy * iyy;
    float trace = ixx * pxx + 2.0f * ixy * pxy + iyy * pyy;
    float pdet  = pxx * pyy - pxy * pxy;
    float term2 = trace + logf(tdet / pdet);

    float kld  = 0.5f * (term1 + term2) - 1.0f;
    float kl   = fmaxf(kld, 1e-6f);
    float loss = 1.0f - 1.0f / (2.0f + sqrtf(kl));

    // ---- Block reduction (deterministic tree) ----
    #pragma unroll
    for (int off = 16; off > 0; off >>= 1)
        loss += __shfl_down_sync(0xffffffffu, loss, off);

    if ((tid & 31) == 0) red[tid >> 5] = loss;
    __syncthreads();

    if (tid < 32) {
        float v = (tid < 8) ? red[tid] : 0.0f;
        #pragma unroll
        for (int off = 4; off > 0; off >>= 1)
            v += __shfl_down_sync(0xffffffffu, v, off);
        if (tid == 0) g_partials[blk] = v;
    }
}

__global__ __launch_bounds__(1024)
void kld_reduce_kernel(float* __restrict__ out)
{
    __shared__ double sd[32];
    const int tid = threadIdx.x;

    double acc = 0.0;
    #pragma unroll
    for (int i = tid; i < NBLOCKS; i += 1024)
        acc += (double)g_partials[i];

    #pragma unroll
    for (int off = 16; off > 0; off >>= 1)
        acc += __shfl_down_sync(0xffffffffu, acc, off);

    if ((tid & 31) == 0) sd[tid >> 5] = acc;
    __syncthreads();

    if (tid < 32) {
        double v = sd[tid];
        #pragma unroll
        for (int off = 16; off > 0; off >>= 1)
            v += __shfl_down_sync(0xffffffffu, v, off);
        if (tid == 0) out[0] = (float)(v / (double)NBOX);
    }
}

extern "C" void kernel_launch(void* const* d_in, const int* in_sizes, int n_in,
                              void* d_out, int out_size)
{
    const float* pred = (const float*)d_in[0];
    const float* tgt  = (const float*)d_in[1];
    float* out = (float*)d_out;

    kld_main_kernel<<<NBLOCKS, BOX_PER_BLK>>>(pred, tgt);
    kld_reduce_kernel<<<1, 1024>>>(out);
}